// round 14
// baseline (speedup 1.0000x reference)
#include <cuda_runtime.h>

// out[b,s,f,o] = sum_{t,k,c} x[b, s+t-2, f*(k+1), c] * W[t,k,c,o],  f*(k+1) < F
// x [4,1024,512,4] f32, W [5,4,4,4] f32, out [4,1024,512,4] f32.
//
// R14: heterogeneous grid. Heavy blocks (bx<1024): smem tile, f<256 only,
//      warp costs {4,4,4,4,3,3,2,2}. Light blocks (bx>=1024): f>=256, k=0,
//      smem-free coalesced gmem ring — they pack the tail wave / SM gaps.
//      FFMA2 o-pair packing (raw W layout -> direct constant memcpy).

#define B_  4
#define S_  1024
#define F_  512
#define U_  4
#define NT  5
#define NK  4
#define TPB 256
#define NH  (B_ * (S_ / U_))     // 1024 heavy blocks
#define NL  (B_ * (S_ / U_))     // 1024 light blocks

typedef unsigned long long u64;

// raw layout: WcR[t][k][c] = (W[t][k][c][0..1], W[t][k][c][2..3]) as o-pairs
__constant__ ulonglong2 WcR[NT][NK][4];

__device__ __forceinline__ u64 fma2(u64 a, u64 b, u64 c) {
    u64 d;
    asm("fma.rn.f32x2 %0, %1, %2, %3;" : "=l"(d) : "l"(a), "l"(b), "l"(c));
    return d;
}
__device__ __forceinline__ u64 dup2(float v) {
    u64 d;
    asm("mov.b64 %0, {%1, %1};" : "=l"(d) : "f"(v));
    return d;
}

struct Row { u64 c0, c1, c2, c3; };

__device__ __forceinline__ Row loadRow(const float4* __restrict__ p) {
    float4 v = *p;
    Row r;
    r.c0 = dup2(v.x); r.c1 = dup2(v.y); r.c2 = dup2(v.z); r.c3 = dup2(v.w);
    return r;
}
__device__ __forceinline__ Row zeroRow() {
    Row r; r.c0 = r.c1 = r.c2 = r.c3 = 0ull; return r;
}

// one harmonic k: 5 taps x 4 outputs over ring-buffered rows of `col`
__device__ __forceinline__ void harmonic(
    const float4* __restrict__ col, int k, u64 acc[U_][2])
{
    Row w4[4];
#pragma unroll
    for (int m = 0; m < 4; ++m) w4[m] = loadRow(col + m * F_);

#pragma unroll
    for (int t = 0; t < NT; ++t) {
        ulonglong2 q0 = WcR[t][k][0];
        ulonglong2 q1 = WcR[t][k][1];
        ulonglong2 q2 = WcR[t][k][2];
        ulonglong2 q3 = WcR[t][k][3];
#pragma unroll
        for (int j = 0; j < U_; ++j) {
            Row rv = w4[(t + j) & 3];
            acc[j][0] = fma2(rv.c0, q0.x, acc[j][0]);
            acc[j][1] = fma2(rv.c0, q0.y, acc[j][1]);
            acc[j][0] = fma2(rv.c1, q1.x, acc[j][0]);
            acc[j][1] = fma2(rv.c1, q1.y, acc[j][1]);
            acc[j][0] = fma2(rv.c2, q2.x, acc[j][0]);
            acc[j][1] = fma2(rv.c2, q2.y, acc[j][1]);
            acc[j][0] = fma2(rv.c3, q3.x, acc[j][0]);
            acc[j][1] = fma2(rv.c3, q3.y, acc[j][1]);
        }
        if (t < NT - 1) w4[t & 3] = loadRow(col + (t + 4) * F_);
    }
}

__device__ __forceinline__ void store4(
    float4* __restrict__ o4, const u64 acc[U_][2])
{
#pragma unroll
    for (int j = 0; j < U_; ++j) {
        float2 lo = reinterpret_cast<const float2&>(acc[j][0]);
        float2 hi = reinterpret_cast<const float2&>(acc[j][1]);
        o4[(size_t)j * F_] = make_float4(lo.x, lo.y, hi.x, hi.y);
    }
}

__global__ __launch_bounds__(TPB, 3) void harm_conv_kernel(
    const float* __restrict__ x,
    float* __restrict__ out)
{
    extern __shared__ float4 tile[];              // heavy: [8][F_] rows
    int bx = blockIdx.x;
    int tid = threadIdx.x;
    const float4* __restrict__ x4 = reinterpret_cast<const float4*>(x);

    if (bx < NH) {
        // ───────── heavy block: f = tid (< 256), full harmonic loop ─────────
        int sb = bx & (S_ / U_ - 1);
        int b  = bx >> 8;
        int s0 = sb * U_;
        const float4* __restrict__ xb = x4 + (size_t)b * S_ * F_;

        // stage 8 full rows (each thread: 2 cols x 8 rows), coalesced
        if (sb > 0 && sb < S_ / U_ - 1) {
            const float4* __restrict__ src = xb + (size_t)(s0 - 2) * F_ + tid;
#pragma unroll
            for (int i = 0; i < U_ + 4; ++i) {
                tile[i * F_ + tid]       = src[(size_t)i * F_];
                tile[i * F_ + tid + TPB] = src[(size_t)i * F_ + TPB];
            }
        } else {
#pragma unroll
            for (int i = 0; i < U_ + 4; ++i) {
                int sp = s0 + i - 2;
                if (sp >= 0 && sp < S_) {
                    tile[i * F_ + tid]       = xb[(size_t)sp * F_ + tid];
                    tile[i * F_ + tid + TPB] = xb[(size_t)sp * F_ + tid + TPB];
                } else {
                    tile[i * F_ + tid]       = make_float4(0.f, 0.f, 0.f, 0.f);
                    tile[i * F_ + tid + TPB] = make_float4(0.f, 0.f, 0.f, 0.f);
                }
            }
        }
        __syncthreads();

        int f = tid;
        u64 acc[U_][2];
#pragma unroll
        for (int j = 0; j < U_; ++j) { acc[j][0] = 0ull; acc[j][1] = 0ull; }

        for (int k = 0; k < NK; ++k) {
            int fk = f * (k + 1);
            if (fk >= F_) break;                  // near-coherent within warp
            harmonic(tile + fk, k, acc);
        }

        float4* __restrict__ o4 =
            reinterpret_cast<float4*>(out) + ((size_t)(b * S_ + s0)) * F_ + f;
        store4(o4, acc);
    } else {
        // ───────── light block: f = 256 + tid, k = 0 only, gmem ring ─────────
        int lb = bx - NH;
        int sb = lb & (S_ / U_ - 1);
        int b  = lb >> 8;
        int s0 = sb * U_;
        int f  = 256 + tid;
        const float4* __restrict__ col = x4 + (size_t)b * S_ * F_ + f;

        Row w4[4];
        bool interior = (sb > 0 && sb < S_ / U_ - 1);
#pragma unroll
        for (int m = 0; m < 4; ++m) {
            int sp = s0 + m - 2;
            w4[m] = (interior || (sp >= 0 && sp < S_))
                  ? loadRow(col + (size_t)sp * F_) : zeroRow();
        }

        u64 acc[U_][2];
#pragma unroll
        for (int j = 0; j < U_; ++j) { acc[j][0] = 0ull; acc[j][1] = 0ull; }

#pragma unroll
        for (int t = 0; t < NT; ++t) {
            ulonglong2 q0 = WcR[t][0][0];
            ulonglong2 q1 = WcR[t][0][1];
            ulonglong2 q2 = WcR[t][0][2];
            ulonglong2 q3 = WcR[t][0][3];
#pragma unroll
            for (int j = 0; j < U_; ++j) {
                Row rv = w4[(t + j) & 3];
                acc[j][0] = fma2(rv.c0, q0.x, acc[j][0]);
                acc[j][1] = fma2(rv.c0, q0.y, acc[j][1]);
                acc[j][0] = fma2(rv.c1, q1.x, acc[j][0]);
                acc[j][1] = fma2(rv.c1, q1.y, acc[j][1]);
                acc[j][0] = fma2(rv.c2, q2.x, acc[j][0]);
                acc[j][1] = fma2(rv.c2, q2.y, acc[j][1]);
                acc[j][0] = fma2(rv.c3, q3.x, acc[j][0]);
                acc[j][1] = fma2(rv.c3, q3.y, acc[j][1]);
            }
            if (t < NT - 1) {
                int sp = s0 + t + 2;
                w4[t & 3] = (interior || sp < S_)
                          ? loadRow(col + (size_t)sp * F_) : zeroRow();
            }
        }

        float4* __restrict__ o4 =
            reinterpret_cast<float4*>(out) + ((size_t)(b * S_ + s0)) * F_ + f;
        store4(o4, acc);
    }
}

extern "C" void kernel_launch(void* const* d_in, const int* in_sizes, int n_in,
                              void* d_out, int out_size)
{
    const float* x = (const float*)d_in[0];
    const float* W = (const float*)d_in[1];
    float* out = (float*)d_out;

    const int SMEM = (U_ + 4) * F_ * 16;          // 64 KB

    (void)cudaFuncSetAttribute(harm_conv_kernel,
                               cudaFuncAttributeMaxDynamicSharedMemorySize,
                               SMEM);

    // raw W layout IS the o-pair packed layout: direct copy, no transpose node
    cudaMemcpyToSymbolAsync(WcR, W, NT * NK * 16 * sizeof(float), 0,
                            cudaMemcpyDeviceToDevice, 0);

    harm_conv_kernel<<<NH + NL, TPB, SMEM>>>(x, out);
}